// round 2
// baseline (speedup 1.0000x reference)
#include <cuda_runtime.h>
#include <math_constants.h>

// Problem constants
#define BB 1024   // batch
#define CC 32     // classes
#define KK 16     // prototypes per class
#define DD 256    // embedding dim
#define TWO_D 512

// Scratch (static device arrays — no allocation allowed)
__device__ float g_proto_term[CC * KK * DD];          // 512 KB: b1 + p @ W1_bottom
__device__ float g_qW[(size_t)CC * BB * DD];          // 33.5 MB: emb @ W1_top
__device__ float g_inval[CC * KK];                    // 0 = valid, -inf = invalid

__device__ __forceinline__ float tanh_fast(float x) {
    float r;
    asm("tanh.approx.f32 %0, %1;" : "=f"(r) : "f"(x));
    return r;
}

// ---------------------------------------------------------------------------
// Kernel 0: decode prototype_valid whatever its storage dtype is.
// The reference dtype is bool; the harness materializes float32/int32/uint8.
// Detect from the first 512 bytes (in-bounds for every candidate):
//   any word == 0x3F800000                  -> float32 (1.0f pattern)
//   any other word with nonzero high bytes  -> uint8 bool (e.g. 0x01010101)
//   else                                    -> int32
// ---------------------------------------------------------------------------
__global__ __launch_bounds__(512) void decode_mask_kernel(const void* __restrict__ valid)
{
    __shared__ int s_hasF, s_hasHi, s_mode;
    const int tid = threadIdx.x;
    if (tid == 0) { s_hasF = 0; s_hasHi = 0; }
    __syncthreads();

    if (tid < 128) {   // first 512 bytes only — safe for uint8/int32/float32
        unsigned v = ((const unsigned*)valid)[tid];
        if (v == 0x3F800000u)                        atomicOr(&s_hasF, 1);
        else if (v != 0u && (v & 0xFFFFFF00u) != 0u) atomicOr(&s_hasHi, 1);
    }
    __syncthreads();
    if (tid == 0) s_mode = s_hasF ? 0 : (s_hasHi ? 2 : 1);
    __syncthreads();

    const int mode = s_mode;
    if (tid < CC * KK) {
        bool v;
        if (mode == 0)      v = ((const float*)valid)[tid] != 0.0f;
        else if (mode == 1) v = ((const int*)valid)[tid] != 0;
        else                v = ((const unsigned char*)valid)[tid] != 0;
        g_inval[tid] = v ? 0.0f : -CUDART_INF_F;
    }
}

// ---------------------------------------------------------------------------
// Kernel 1: proto_term[c][k][d] = b1[c][d] + sum_e proto[c][k][e] * W1[c][D+e][d]
// grid (4, C), 256 threads; each block handles 4 prototypes of one class.
// ---------------------------------------------------------------------------
__global__ __launch_bounds__(256) void proto_term_kernel(
    const float* __restrict__ protos,   // [C,K,D]
    const float* __restrict__ W1,       // [C,2D,D]
    const float* __restrict__ b1)       // [C,D]
{
    const int c  = blockIdx.y;
    const int kq = blockIdx.x;          // k quarter: handles k = kq*4 .. kq*4+3
    const int d  = threadIdx.x;

    __shared__ float p_s[4][DD];
    #pragma unroll
    for (int i = 0; i < 4; ++i)
        p_s[i][d] = protos[((c * KK) + kq * 4 + i) * DD + d];
    __syncthreads();

    const float* Wb = W1 + ((size_t)c * TWO_D + DD) * DD + d;  // bottom half, column d
    float b1v = b1[c * DD + d];
    float acc0 = b1v, acc1 = b1v, acc2 = b1v, acc3 = b1v;

    #pragma unroll 4
    for (int e = 0; e < DD; ++e) {
        float w = Wb[e * DD];
        acc0 = fmaf(p_s[0][e], w, acc0);
        acc1 = fmaf(p_s[1][e], w, acc1);
        acc2 = fmaf(p_s[2][e], w, acc2);
        acc3 = fmaf(p_s[3][e], w, acc3);
    }
    float* out = g_proto_term + ((c * KK) + kq * 4) * DD + d;
    out[0 * DD] = acc0; out[1 * DD] = acc1; out[2 * DD] = acc2; out[3 * DD] = acc3;
}

// ---------------------------------------------------------------------------
// Kernel 2: qW[c][b][d] = sum_e emb[b][e] * W1[c][e][d]
// Classic fp32 SGEMM: 128x128 block tile, BK=8, 256 threads, 8x8 per thread,
// register prefetch of next global tile.
// grid (2 N-tiles, 8 M-tiles, 32 classes)
// ---------------------------------------------------------------------------
__global__ __launch_bounds__(256) void qw_gemm_kernel(
    const float* __restrict__ emb,      // [B,D]
    const float* __restrict__ W1)       // [C,2D,D]
{
    const int c   = blockIdx.z;
    const int bn0 = blockIdx.x * 128;
    const int bm0 = blockIdx.y * 128;

    const float* A  = emb;                         // [1024,256]
    const float* Bm = W1 + (size_t)c * TWO_D * DD; // top [256,256] row-major

    __shared__ float As[8][128];   // [k][m] (transposed)
    __shared__ float Bs[8][128];   // [k][n]

    const int tid = threadIdx.x;
    const int tx  = tid & 15;      // 0..15 -> n
    const int ty  = tid >> 4;      // 0..15 -> m

    // global-load assignments (one float4 each)
    const int a_r = tid >> 1;            // 0..127
    const int a_c = (tid & 1) * 4;       // 0 or 4
    const int b_r = tid >> 5;            // 0..7
    const int b_c = (tid & 31) * 4;      // 0..124

    float acc[8][8];
    #pragma unroll
    for (int i = 0; i < 8; ++i)
        #pragma unroll
        for (int j = 0; j < 8; ++j) acc[i][j] = 0.f;

    float4 ra = *(const float4*)(A  + (bm0 + a_r) * DD + a_c);
    float4 rb = *(const float4*)(Bm + b_r * DD + bn0 + b_c);

    for (int kt = 0; kt < DD / 8; ++kt) {
        As[a_c + 0][a_r] = ra.x;
        As[a_c + 1][a_r] = ra.y;
        As[a_c + 2][a_r] = ra.z;
        As[a_c + 3][a_r] = ra.w;
        *(float4*)&Bs[b_r][b_c] = rb;
        __syncthreads();

        if (kt + 1 < DD / 8) {
            int k0 = (kt + 1) * 8;
            ra = *(const float4*)(A  + (bm0 + a_r) * DD + k0 + a_c);
            rb = *(const float4*)(Bm + (k0 + b_r) * DD + bn0 + b_c);
        }

        #pragma unroll
        for (int kk = 0; kk < 8; ++kk) {
            float a_[8], b_[8];
            *(float4*)(a_ + 0) = *(const float4*)&As[kk][ty * 8 + 0];
            *(float4*)(a_ + 4) = *(const float4*)&As[kk][ty * 8 + 4];
            *(float4*)(b_ + 0) = *(const float4*)&Bs[kk][tx * 8 + 0];
            *(float4*)(b_ + 4) = *(const float4*)&Bs[kk][tx * 8 + 4];
            #pragma unroll
            for (int i = 0; i < 8; ++i)
                #pragma unroll
                for (int j = 0; j < 8; ++j)
                    acc[i][j] = fmaf(a_[i], b_[j], acc[i][j]);
        }
        __syncthreads();
    }

    float* out = g_qW + ((size_t)c * BB + bm0 + ty * 8) * DD + bn0 + tx * 8;
    #pragma unroll
    for (int i = 0; i < 8; ++i) {
        float4 v0 = make_float4(acc[i][0], acc[i][1], acc[i][2], acc[i][3]);
        float4 v1 = make_float4(acc[i][4], acc[i][5], acc[i][6], acc[i][7]);
        *(float4*)(out + i * DD + 0) = v0;
        *(float4*)(out + i * DD + 4) = v1;
    }
}

// ---------------------------------------------------------------------------
// Kernel 3: fused scores -> softmax over K -> attn-weighted prototype ->
//           euclidean distance -> out[b][c] = -dist * temperature
// grid (B/32, C), 256 threads (8 warps), each warp handles 4 batch rows.
// ---------------------------------------------------------------------------
__global__ __launch_bounds__(256) void attend_kernel(
    const float* __restrict__ emb,        // [B,D]
    const float* __restrict__ protos,     // [C,K,D]
    const float* __restrict__ w2,         // [C,D]
    const float* __restrict__ b2,         // [C]
    const float* __restrict__ temperature,// [1]
    float* __restrict__ out)              // [B,C]
{
    const int c  = blockIdx.y;
    const int b0 = blockIdx.x * 32;
    const int tid = threadIdx.x;
    const int warp = tid >> 5;
    const int lane = tid & 31;

    __shared__ float pt_s[KK][DD];   // 16 KB
    __shared__ float p_s[KK][DD];    // 16 KB
    __shared__ float w2_s[DD];       // 1 KB
    __shared__ float inval_s[KK];    // 0 = valid, -inf = invalid

    // cooperative loads
    for (int i = tid; i < KK * DD; i += 256) {
        pt_s[0][i] = g_proto_term[(size_t)c * KK * DD + i];
        p_s[0][i]  = protos[(size_t)c * KK * DD + i];
    }
    if (tid < DD) w2_s[tid] = w2[c * DD + tid];
    if (tid < KK) inval_s[tid] = g_inval[c * KK + tid];
    __syncthreads();

    const float b2v  = b2[c];
    const float temp = temperature[0];

    for (int ib = 0; ib < 4; ++ib) {
        const int b = b0 + warp * 4 + ib;

        // per-lane slice of d: float4 at d = 4*lane + 128*j  (j = 0,1)
        float4 q4[2], e4[2], w24[2];
        #pragma unroll
        for (int j = 0; j < 2; ++j) {
            int d = 4 * lane + 128 * j;
            q4[j]  = *(const float4*)(g_qW + ((size_t)c * BB + b) * DD + d);
            e4[j]  = *(const float4*)(emb + (size_t)b * DD + d);
            w24[j] = *(const float4*)(w2_s + d);
        }

        // scores over K
        float s16[KK];
        #pragma unroll
        for (int k = 0; k < KK; ++k) {
            float s = 0.f;
            #pragma unroll
            for (int j = 0; j < 2; ++j) {
                int d = 4 * lane + 128 * j;
                float4 pt4 = *(const float4*)(&pt_s[k][d]);
                const float* qv = (const float*)&q4[j];
                const float* wv = (const float*)&w24[j];
                const float* pv = (const float*)&pt4;
                #pragma unroll
                for (int i = 0; i < 4; ++i) {
                    float t = tanh_fast(qv[i] + pv[i]);
                    s = fmaf(wv[i], t, s);
                }
            }
            // butterfly reduce — all lanes get the sum
            #pragma unroll
            for (int off = 16; off > 0; off >>= 1)
                s += __shfl_xor_sync(0xFFFFFFFFu, s, off);
            s16[k] = s + b2v + inval_s[k];
        }

        // softmax over K
        float m = s16[0];
        #pragma unroll
        for (int k = 1; k < KK; ++k) m = fmaxf(m, s16[k]);
        float sum = 0.f;
        #pragma unroll
        for (int k = 0; k < KK; ++k) {
            float e = __expf(s16[k] - m);
            s16[k] = e;
            sum += e;
        }
        float inv = 1.f / sum;
        #pragma unroll
        for (int k = 0; k < KK; ++k) s16[k] *= inv;

        // attn-weighted prototype, diff, squared distance
        float ss = 0.f;
        #pragma unroll
        for (int j = 0; j < 2; ++j) {
            int d = 4 * lane + 128 * j;
            float fp[4] = {0.f, 0.f, 0.f, 0.f};
            #pragma unroll
            for (int k = 0; k < KK; ++k) {
                float4 pv = *(const float4*)(&p_s[k][d]);
                fp[0] = fmaf(s16[k], pv.x, fp[0]);
                fp[1] = fmaf(s16[k], pv.y, fp[1]);
                fp[2] = fmaf(s16[k], pv.z, fp[2]);
                fp[3] = fmaf(s16[k], pv.w, fp[3]);
            }
            const float* ev = (const float*)&e4[j];
            #pragma unroll
            for (int i = 0; i < 4; ++i) {
                float diff = ev[i] - fp[i];
                ss = fmaf(diff, diff, ss);
            }
        }
        #pragma unroll
        for (int off = 16; off > 0; off >>= 1)
            ss += __shfl_xor_sync(0xFFFFFFFFu, ss, off);

        if (lane == 0)
            out[(size_t)b * CC + c] = -sqrtf(ss) * temp;
    }
}

// ---------------------------------------------------------------------------
extern "C" void kernel_launch(void* const* d_in, const int* in_sizes, int n_in,
                              void* d_out, int out_size)
{
    const float* emb    = (const float*)d_in[0];   // [B,D]
    const float* protos = (const float*)d_in[1];   // [C,K,D]
    const float* W1     = (const float*)d_in[2];   // [C,2D,D]
    const float* b1     = (const float*)d_in[3];   // [C,D]
    const float* w2     = (const float*)d_in[4];   // [C,D]
    const float* b2     = (const float*)d_in[5];   // [C]
    const float* temp   = (const float*)d_in[6];   // [1]
    const void*  valid  = (const void*)d_in[7];    // [C,K] bool (storage dtype unknown)
    float* out = (float*)d_out;                    // [B,C]

    decode_mask_kernel<<<1, 512>>>(valid);
    proto_term_kernel<<<dim3(4, CC), 256>>>(protos, W1, b1);
    qw_gemm_kernel<<<dim3(2, 8, CC), 256>>>(emb, W1);
    attend_kernel<<<dim3(BB / 32, CC), 256>>>(emb, protos, w2, b2, temp, out);
}

// round 3
// speedup vs baseline: 1.2859x; 1.2859x over previous
#include <cuda_runtime.h>
#include <math_constants.h>
#include <cstdint>

// Problem constants
#define BB 1024   // batch
#define CC 32     // classes
#define KK 16     // prototypes per class
#define DD 256    // embedding dim
#define TWO_D 512

// Scratch (static device arrays — no allocation allowed)
__device__ float g_proto_term[CC * KK * DD];          // 512 KB
__device__ float g_qW[(size_t)CC * BB * DD];          // 33.5 MB
__device__ float g_dotep[(size_t)BB * CC * KK];       // 2 MB: emb·proto
__device__ float g_G[CC * KK * KK];                   // 32 KB: Gram
__device__ float g_e2[BB];                            // |emb|^2
__device__ float g_inval[CC * KK];                    // 0 = valid, -inf = invalid

__device__ __forceinline__ float tanh_fast(float x) {
    float r;
    asm("tanh.approx.f32 %0, %1;" : "=f"(r) : "f"(x));
    return r;
}
__device__ __forceinline__ uint32_t f2tf(float f) {
    uint32_t r;
    asm("cvt.rna.tf32.f32 %0, %1;" : "=r"(r) : "f"(f));
    return r;
}
__device__ __forceinline__ void cp16(void* smem, const void* g) {
    uint32_t sa = (uint32_t)__cvta_generic_to_shared(smem);
    asm volatile("cp.async.cg.shared.global [%0], [%1], 16;" :: "r"(sa), "l"(g));
}
#define CP_COMMIT() asm volatile("cp.async.commit_group;")
#define CP_WAIT(N)  asm volatile("cp.async.wait_group %0;" :: "n"(N))

__device__ __forceinline__ void mma_tf32(float c_[4], const uint32_t a[4], const uint32_t b[2]) {
    asm volatile(
        "mma.sync.aligned.m16n8k8.row.col.f32.tf32.tf32.f32 "
        "{%0,%1,%2,%3}, {%4,%5,%6,%7}, {%8,%9}, {%0,%1,%2,%3};"
        : "+f"(c_[0]), "+f"(c_[1]), "+f"(c_[2]), "+f"(c_[3])
        : "r"(a[0]), "r"(a[1]), "r"(a[2]), "r"(a[3]), "r"(b[0]), "r"(b[1]));
}

// ---------------------------------------------------------------------------
// Kernel 0: decode prototype_valid whatever its storage dtype is.
// ---------------------------------------------------------------------------
__global__ __launch_bounds__(512) void decode_mask_kernel(const void* __restrict__ valid)
{
    __shared__ int s_hasF, s_hasHi, s_mode;
    const int tid = threadIdx.x;
    if (tid == 0) { s_hasF = 0; s_hasHi = 0; }
    __syncthreads();
    if (tid < 128) {   // first 512 bytes only — safe for uint8/int32/float32
        unsigned v = ((const unsigned*)valid)[tid];
        if (v == 0x3F800000u)                        atomicOr(&s_hasF, 1);
        else if (v != 0u && (v & 0xFFFFFF00u) != 0u) atomicOr(&s_hasHi, 1);
    }
    __syncthreads();
    if (tid == 0) s_mode = s_hasF ? 0 : (s_hasHi ? 2 : 1);
    __syncthreads();
    const int mode = s_mode;
    if (tid < CC * KK) {
        bool v;
        if (mode == 0)      v = ((const float*)valid)[tid] != 0.0f;
        else if (mode == 1) v = ((const int*)valid)[tid] != 0;
        else                v = ((const unsigned char*)valid)[tid] != 0;
        g_inval[tid] = v ? 0.0f : -CUDART_INF_F;
    }
}

// ---------------------------------------------------------------------------
// Kernel 1: proto_term[c][k][d] = b1[c][d] + sum_e proto[c][k][e]*W1[c][D+e][d]
// grid (2, C): 8 prototypes per block.
// ---------------------------------------------------------------------------
__global__ __launch_bounds__(256) void proto_term_kernel(
    const float* __restrict__ protos, const float* __restrict__ W1,
    const float* __restrict__ b1)
{
    const int c  = blockIdx.y;
    const int kh = blockIdx.x;          // k half: k = kh*8 .. kh*8+7
    const int d  = threadIdx.x;

    __shared__ float p_s[8][DD];
    #pragma unroll
    for (int i = 0; i < 8; ++i)
        p_s[i][d] = protos[((c * KK) + kh * 8 + i) * DD + d];
    __syncthreads();

    const float* Wb = W1 + ((size_t)c * TWO_D + DD) * DD + d;
    float b1v = b1[c * DD + d];
    float acc[8];
    #pragma unroll
    for (int i = 0; i < 8; ++i) acc[i] = b1v;

    #pragma unroll 2
    for (int e = 0; e < DD; ++e) {
        float w = Wb[e * DD];
        #pragma unroll
        for (int i = 0; i < 8; ++i) acc[i] = fmaf(p_s[i][e], w, acc[i]);
    }
    #pragma unroll
    for (int i = 0; i < 8; ++i)
        g_proto_term[((c * KK) + kh * 8 + i) * DD + d] = acc[i];
}

// ---------------------------------------------------------------------------
// Kernel 2: Gram G[c][k][k'] = proto[c,k]·proto[c,k'] ; grid CC, 256 thr.
// ---------------------------------------------------------------------------
__global__ __launch_bounds__(256) void gram_kernel(const float* __restrict__ protos)
{
    const int c = blockIdx.x;
    const int tid = threadIdx.x;
    __shared__ float p_s[KK][DD + 1];
    for (int i = tid; i < KK * DD; i += 256) {
        int k = i / DD, d = i % DD;
        p_s[k][d] = protos[(size_t)c * KK * DD + i];
    }
    __syncthreads();
    const int k = tid >> 4, k2 = tid & 15;
    float s = 0.f;
    #pragma unroll 4
    for (int d = 0; d < DD; ++d) s = fmaf(p_s[k][d], p_s[k2][d], s);
    g_G[c * 256 + tid] = s;
}

// ---------------------------------------------------------------------------
// Kernel 3: e2[b] = |emb[b]|^2 ; grid 8, 128 thr.
// ---------------------------------------------------------------------------
__global__ __launch_bounds__(128) void e2_kernel(const float* __restrict__ emb)
{
    const int b = blockIdx.x * 128 + threadIdx.x;
    const float4* p = (const float4*)(emb + (size_t)b * DD);
    float s = 0.f;
    #pragma unroll 8
    for (int i = 0; i < DD / 4; ++i) {
        float4 v = p[i];
        s = fmaf(v.x, v.x, s); s = fmaf(v.y, v.y, s);
        s = fmaf(v.z, v.z, s); s = fmaf(v.w, v.w, s);
    }
    g_e2[b] = s;
}

// ---------------------------------------------------------------------------
// Kernel 4: qW[c][b][d] = emb[b,:] @ W1[c,:D,:]   (tf32 tensor-core GEMM)
// Block tile 128x128, BK=16 double-buffered cp.async, 128 thr (4 warps 2x2),
// warp tile 64x64 (4 m-tiles x 8 n-tiles of m16n8k8).
// grid (2 Ntiles, 8 Mtiles, 32 classes)
// ---------------------------------------------------------------------------
#define QW_BK 16
__global__ __launch_bounds__(128) void qw_gemm_tf32(
    const float* __restrict__ emb, const float* __restrict__ W1)
{
    const int c   = blockIdx.z;
    const int bn0 = blockIdx.x * 128;
    const int bm0 = blockIdx.y * 128;
    const float* A  = emb;
    const float* Bm = W1 + (size_t)c * TWO_D * DD;   // top half [256 k][256 n]

    __shared__ __align__(16) float As[2][128][QW_BK + 4];   // [m][k]
    __shared__ __align__(16) float Bs[2][QW_BK][128 + 4];   // [k][n]

    const int tid  = threadIdx.x;
    const int warp = tid >> 5, lane = tid & 31;
    const int wm = (warp >> 1) * 64;
    const int wn = (warp & 1) * 64;
    const int g  = lane >> 2, tg = lane & 3;

    float acc[4][8][4];
    #pragma unroll
    for (int i = 0; i < 4; ++i)
        #pragma unroll
        for (int j = 0; j < 8; ++j)
            #pragma unroll
            for (int t = 0; t < 4; ++t) acc[i][j][t] = 0.f;

    // stage loader
    #define QW_LOAD(s, kbase)                                                   \
        {                                                                        \
            _Pragma("unroll")                                                    \
            for (int i_ = 0; i_ < 4; ++i_) {                                     \
                int slot = tid + i_ * 128;                                       \
                int m = slot >> 2, k4 = (slot & 3) << 2;                         \
                cp16(&As[s][m][k4], A + (size_t)(bm0 + m) * DD + (kbase) + k4);  \
            }                                                                    \
            _Pragma("unroll")                                                    \
            for (int i_ = 0; i_ < 4; ++i_) {                                     \
                int slot = tid + i_ * 128;                                       \
                int k = slot >> 5, n4 = (slot & 31) << 2;                        \
                cp16(&Bs[s][k][n4], Bm + (size_t)((kbase) + k) * DD + bn0 + n4); \
            }                                                                    \
            CP_COMMIT();                                                         \
        }

    QW_LOAD(0, 0);
    int s = 0;
    const int NT = DD / QW_BK;   // 16
    for (int kt = 0; kt < NT; ++kt) {
        if (kt + 1 < NT) { QW_LOAD(s ^ 1, (kt + 1) * QW_BK); CP_WAIT(1); }
        else             { CP_WAIT(0); }
        __syncthreads();

        #pragma unroll
        for (int ks = 0; ks < 2; ++ks) {
            const int kb = ks * 8;
            uint32_t afr[4][4], bfr[8][2];
            #pragma unroll
            for (int i = 0; i < 4; ++i) {
                int m0 = wm + i * 16;
                afr[i][0] = f2tf(As[s][m0 + g][kb + tg]);
                afr[i][1] = f2tf(As[s][m0 + g + 8][kb + tg]);
                afr[i][2] = f2tf(As[s][m0 + g][kb + tg + 4]);
                afr[i][3] = f2tf(As[s][m0 + g + 8][kb + tg + 4]);
            }
            #pragma unroll
            for (int j = 0; j < 8; ++j) {
                int n0 = wn + j * 8;
                bfr[j][0] = f2tf(Bs[s][kb + tg][n0 + g]);
                bfr[j][1] = f2tf(Bs[s][kb + tg + 4][n0 + g]);
            }
            #pragma unroll
            for (int i = 0; i < 4; ++i)
                #pragma unroll
                for (int j = 0; j < 8; ++j)
                    mma_tf32(acc[i][j], afr[i], bfr[j]);
        }
        __syncthreads();
        s ^= 1;
    }

    float* outB = g_qW + (size_t)c * BB * DD;
    #pragma unroll
    for (int i = 0; i < 4; ++i) {
        int r0 = bm0 + wm + i * 16 + g;
        #pragma unroll
        for (int j = 0; j < 8; ++j) {
            int col = bn0 + wn + j * 8 + 2 * tg;
            *(float2*)(outB + (size_t)r0 * DD + col)       = make_float2(acc[i][j][0], acc[i][j][1]);
            *(float2*)(outB + (size_t)(r0 + 8) * DD + col) = make_float2(acc[i][j][2], acc[i][j][3]);
        }
    }
    #undef QW_LOAD
}

// ---------------------------------------------------------------------------
// Kernel 5: dotep[b][ck] = emb[b,:]·proto[ck,:]   (tf32 mma, B naturally col-major)
// Block tile 64x64, BK=16 double-buffered, 128 thr (4 warps 2x2), warp 32x32.
// grid (8 Ntiles, 16 Mtiles)
// ---------------------------------------------------------------------------
__global__ __launch_bounds__(128) void dotep_gemm_tf32(
    const float* __restrict__ emb, const float* __restrict__ protos)
{
    const int bn0 = blockIdx.x * 64;   // over 512 protos
    const int bm0 = blockIdx.y * 64;   // over 1024 batch

    __shared__ __align__(16) float As[2][64][QW_BK + 4];   // [m][k]
    __shared__ __align__(16) float Ps[2][64][QW_BK + 4];   // [n][k]

    const int tid  = threadIdx.x;
    const int warp = tid >> 5, lane = tid & 31;
    const int wm = (warp >> 1) * 32;
    const int wn = (warp & 1) * 32;
    const int g  = lane >> 2, tg = lane & 3;

    float acc[2][4][4];
    #pragma unroll
    for (int i = 0; i < 2; ++i)
        #pragma unroll
        for (int j = 0; j < 4; ++j)
            #pragma unroll
            for (int t = 0; t < 4; ++t) acc[i][j][t] = 0.f;

    #define DE_LOAD(s, kbase)                                                        \
        {                                                                             \
            _Pragma("unroll")                                                         \
            for (int i_ = 0; i_ < 2; ++i_) {                                          \
                int slot = tid + i_ * 128;                                            \
                int m = slot >> 2, k4 = (slot & 3) << 2;                              \
                cp16(&As[s][m][k4], emb + (size_t)(bm0 + m) * DD + (kbase) + k4);     \
                cp16(&Ps[s][m][k4], protos + (size_t)(bn0 + m) * DD + (kbase) + k4);  \
            }                                                                         \
            CP_COMMIT();                                                              \
        }

    DE_LOAD(0, 0);
    int s = 0;
    const int NT = DD / QW_BK;
    for (int kt = 0; kt < NT; ++kt) {
        if (kt + 1 < NT) { DE_LOAD(s ^ 1, (kt + 1) * QW_BK); CP_WAIT(1); }
        else             { CP_WAIT(0); }
        __syncthreads();

        #pragma unroll
        for (int ks = 0; ks < 2; ++ks) {
            const int kb = ks * 8;
            uint32_t afr[2][4], bfr[4][2];
            #pragma unroll
            for (int i = 0; i < 2; ++i) {
                int m0 = wm + i * 16;
                afr[i][0] = f2tf(As[s][m0 + g][kb + tg]);
                afr[i][1] = f2tf(As[s][m0 + g + 8][kb + tg]);
                afr[i][2] = f2tf(As[s][m0 + g][kb + tg + 4]);
                afr[i][3] = f2tf(As[s][m0 + g + 8][kb + tg + 4]);
            }
            #pragma unroll
            for (int j = 0; j < 4; ++j) {
                int n0 = wn + j * 8;
                bfr[j][0] = f2tf(Ps[s][n0 + g][kb + tg]);
                bfr[j][1] = f2tf(Ps[s][n0 + g][kb + tg + 4]);
            }
            #pragma unroll
            for (int i = 0; i < 2; ++i)
                #pragma unroll
                for (int j = 0; j < 4; ++j)
                    mma_tf32(acc[i][j], afr[i], bfr[j]);
        }
        __syncthreads();
        s ^= 1;
    }

    #pragma unroll
    for (int i = 0; i < 2; ++i) {
        int r0 = bm0 + wm + i * 16 + g;
        #pragma unroll
        for (int j = 0; j < 4; ++j) {
            int col = bn0 + wn + j * 8 + 2 * tg;
            *(float2*)(g_dotep + (size_t)r0 * (CC * KK) + col)       = make_float2(acc[i][j][0], acc[i][j][1]);
            *(float2*)(g_dotep + (size_t)(r0 + 8) * (CC * KK) + col) = make_float2(acc[i][j][2], acc[i][j][3]);
        }
    }
    #undef DE_LOAD
}

// ---------------------------------------------------------------------------
// Kernel 6: fused scores -> softmax -> dist via Gram trick
// grid (B/32, C), 256 threads (8 warps), warp handles 4 batch rows.
// ---------------------------------------------------------------------------
__global__ __launch_bounds__(256) void attend_kernel(
    const float* __restrict__ w2, const float* __restrict__ b2,
    const float* __restrict__ temperature, float* __restrict__ out)
{
    const int c  = blockIdx.y;
    const int b0 = blockIdx.x * 32;
    const int tid = threadIdx.x;
    const int warp = tid >> 5;
    const int lane = tid & 31;

    __shared__ float pt_s[KK][DD];      // 16 KB
    __shared__ float w2_s[DD];
    __shared__ float G_s[KK][KK + 1];
    __shared__ float dotep_s[32][KK];
    __shared__ float e2_s[32];
    __shared__ float inval_s[KK];

    for (int i = tid; i < KK * DD; i += 256)
        pt_s[0][i] = g_proto_term[(size_t)c * KK * DD + i];
    if (tid < DD) w2_s[tid] = w2[c * DD + tid];
    if (tid < KK) inval_s[tid] = g_inval[c * KK + tid];
    if (tid < 256) G_s[tid >> 4][tid & 15] = g_G[c * 256 + tid];
    for (int i = tid; i < 32 * KK; i += 256) {
        int r = i >> 4, k = i & 15;
        dotep_s[r][k] = g_dotep[(size_t)(b0 + r) * (CC * KK) + c * KK + k];
    }
    if (tid < 32) e2_s[tid] = g_e2[b0 + tid];
    __syncthreads();

    const float b2v  = b2[c];
    const float temp = temperature[0];

    for (int ib = 0; ib < 4; ++ib) {
        const int wb = warp * 4 + ib;
        const int b  = b0 + wb;

        float4 q4[2], w24[2];
        #pragma unroll
        for (int j = 0; j < 2; ++j) {
            int d = 4 * lane + 128 * j;
            q4[j]  = *(const float4*)(g_qW + ((size_t)c * BB + b) * DD + d);
            w24[j] = *(const float4*)(w2_s + d);
        }

        // scores over K (tanh part — irreducible MUFU work)
        float s16[KK];
        #pragma unroll
        for (int k = 0; k < KK; ++k) {
            float s = 0.f;
            #pragma unroll
            for (int j = 0; j < 2; ++j) {
                int d = 4 * lane + 128 * j;
                float4 pt4 = *(const float4*)(&pt_s[k][d]);
                const float* qv = (const float*)&q4[j];
                const float* wv = (const float*)&w24[j];
                const float* pv = (const float*)&pt4;
                #pragma unroll
                for (int i = 0; i < 4; ++i) {
                    float t = tanh_fast(qv[i] + pv[i]);
                    s = fmaf(wv[i], t, s);
                }
            }
            #pragma unroll
            for (int off = 16; off > 0; off >>= 1)
                s += __shfl_xor_sync(0xFFFFFFFFu, s, off);
            s16[k] = s + b2v + inval_s[k];
        }

        // softmax over K (all lanes identical)
        float m = s16[0];
        #pragma unroll
        for (int k = 1; k < KK; ++k) m = fmaxf(m, s16[k]);
        float sum = 0.f;
        #pragma unroll
        for (int k = 0; k < KK; ++k) {
            float e = __expf(s16[k] - m);
            s16[k] = e;
            sum += e;
        }
        float inv = 1.f / sum;
        #pragma unroll
        for (int k = 0; k < KK; ++k) s16[k] *= inv;

        // dist^2 = e2 - 2*sum_k attn_k dotep_k + attn^T G attn
        const int kq = lane & 15, kh = lane >> 4;
        float v = 0.f;
        #pragma unroll
        for (int j = 0; j < 8; ++j)
            v = fmaf(G_s[kq][kh * 8 + j], s16[kh * 8 + j], v);
        float r = v * s16[kq];
        if (kh == 0) r -= 2.0f * s16[kq] * dotep_s[wb][kq];
        #pragma unroll
        for (int off = 16; off > 0; off >>= 1)
            r += __shfl_xor_sync(0xFFFFFFFFu, r, off);

        if (lane == 0) {
            float dist2 = fmaxf(e2_s[wb] + r, 0.f);
            out[(size_t)b * CC + c] = -sqrtf(dist2) * temp;
        }
    }
}

// ---------------------------------------------------------------------------
extern "C" void kernel_launch(void* const* d_in, const int* in_sizes, int n_in,
                              void* d_out, int out_size)
{
    const float* emb    = (const float*)d_in[0];   // [B,D]
    const float* protos = (const float*)d_in[1];   // [C,K,D]
    const float* W1     = (const float*)d_in[2];   // [C,2D,D]
    const float* b1     = (const float*)d_in[3];   // [C,D]
    const float* w2     = (const float*)d_in[4];   // [C,D]
    const float* b2     = (const float*)d_in[5];   // [C]
    const float* temp   = (const float*)d_in[6];   // [1]
    const void*  valid  = (const void*)d_in[7];    // [C,K] bool (storage dtype unknown)
    float* out = (float*)d_out;                    // [B,C]

    decode_mask_kernel<<<1, 512>>>(valid);
    proto_term_kernel<<<dim3(2, CC), 256>>>(protos, W1, b1);
    gram_kernel<<<CC, 256>>>(protos);
    e2_kernel<<<BB / 128, 128>>>(emb);
    qw_gemm_tf32<<<dim3(2, 8, CC), 128>>>(emb, W1);
    dotep_gemm_tf32<<<dim3(8, 16), 128>>>(emb, protos);
    attend_kernel<<<dim3(BB / 32, CC), 256>>>(w2, b2, temp, out);
}

// round 4
// speedup vs baseline: 1.4853x; 1.1551x over previous
#include <cuda_runtime.h>
#include <math_constants.h>
#include <cstdint>

// Problem constants
#define BB 1024   // batch
#define CC 32     // classes
#define KK 16     // prototypes per class
#define DD 256    // embedding dim
#define TWO_D 512

// Scratch (static device arrays — no allocation allowed)
__device__ float g_proto_term[CC * KK * DD];          // 512 KB
__device__ float g_dotep[(size_t)BB * CC * KK];       // 2 MB: emb·proto
__device__ float g_G[CC * KK * KK];                   // 32 KB: Gram
__device__ float g_e2[BB];                            // |emb|^2
__device__ float g_inval[CC * KK];                    // 0 = valid, -inf = invalid

__device__ __forceinline__ float tanh_fast(float x) {
    float r;
    asm("tanh.approx.f32 %0, %1;" : "=f"(r) : "f"(x));
    return r;
}
__device__ __forceinline__ uint32_t f2tf(float f) {
    uint32_t r;
    asm("cvt.rna.tf32.f32 %0, %1;" : "=r"(r) : "f"(f));
    return r;
}
__device__ __forceinline__ void cp16(void* smem, const void* g) {
    uint32_t sa = (uint32_t)__cvta_generic_to_shared(smem);
    asm volatile("cp.async.cg.shared.global [%0], [%1], 16;" :: "r"(sa), "l"(g));
}
#define CP_COMMIT() asm volatile("cp.async.commit_group;")
#define CP_WAIT(N)  asm volatile("cp.async.wait_group %0;" :: "n"(N))

__device__ __forceinline__ void mma_tf32(float c_[4], const uint32_t a[4], const uint32_t b[2]) {
    asm volatile(
        "mma.sync.aligned.m16n8k8.row.col.f32.tf32.tf32.f32 "
        "{%0,%1,%2,%3}, {%4,%5,%6,%7}, {%8,%9}, {%0,%1,%2,%3};"
        : "+f"(c_[0]), "+f"(c_[1]), "+f"(c_[2]), "+f"(c_[3])
        : "r"(a[0]), "r"(a[1]), "r"(a[2]), "r"(a[3]), "r"(b[0]), "r"(b[1]));
}

// ===========================================================================
// Kernel A (prologue, fused): blockIdx dispatch
//   blocks [0,64)   : proto_term  (c = blk>>1, kh = blk&1, 8 protos each)
//   blocks [64,96)  : Gram        (c = blk-64)
//   blocks [96,128) : e2          (32 rows per block, warp-per-row x4)
//   block  128      : decode prototype_valid mask
// ===========================================================================
__global__ __launch_bounds__(256) void prologue_kernel(
    const float* __restrict__ emb,      // [B,D]
    const float* __restrict__ protos,   // [C,K,D]
    const float* __restrict__ W1,       // [C,2D,D]
    const float* __restrict__ b1,       // [C,D]
    const void*  __restrict__ valid)
{
    __shared__ float sh[KK * (DD + 1)];   // 16.4 KB, reused per role
    const int blk = blockIdx.x;
    const int tid = threadIdx.x;

    if (blk < 64) {
        // ----- proto_term[c][k][d] = b1[c][d] + sum_e proto[c][k][e]*W1[c][D+e][d]
        const int c  = blk >> 1;
        const int kh = blk & 1;
        const int d  = tid;
        #pragma unroll
        for (int i = 0; i < 8; ++i)
            sh[i * DD + d] = protos[((c * KK) + kh * 8 + i) * DD + d];
        __syncthreads();

        const float* Wb = W1 + ((size_t)c * TWO_D + DD) * DD + d;
        float b1v = b1[c * DD + d];
        float acc[8];
        #pragma unroll
        for (int i = 0; i < 8; ++i) acc[i] = b1v;
        #pragma unroll 2
        for (int e = 0; e < DD; ++e) {
            float w = Wb[e * DD];
            #pragma unroll
            for (int i = 0; i < 8; ++i) acc[i] = fmaf(sh[i * DD + e], w, acc[i]);
        }
        #pragma unroll
        for (int i = 0; i < 8; ++i)
            g_proto_term[((c * KK) + kh * 8 + i) * DD + d] = acc[i];

    } else if (blk < 96) {
        // ----- Gram G[c][k][k2]
        const int c = blk - 64;
        for (int i = tid; i < KK * DD; i += 256) {
            int k = i / DD, d = i % DD;
            sh[k * (DD + 1) + d] = protos[(size_t)c * KK * DD + i];
        }
        __syncthreads();
        const int k = tid >> 4, k2 = tid & 15;
        float s = 0.f;
        #pragma unroll 4
        for (int d = 0; d < DD; ++d)
            s = fmaf(sh[k * (DD + 1) + d], sh[k2 * (DD + 1) + d], s);
        g_G[c * 256 + tid] = s;

    } else if (blk < 128) {
        // ----- e2: warp-per-row, 4 rows per warp
        const int warp = tid >> 5, lane = tid & 31;
        const int base = (blk - 96) * 32 + warp * 4;
        #pragma unroll
        for (int t = 0; t < 4; ++t) {
            const int b = base + t;
            const float4* p = (const float4*)(emb + (size_t)b * DD);
            float4 v0 = p[lane], v1 = p[lane + 32];
            float s = v0.x*v0.x + v0.y*v0.y + v0.z*v0.z + v0.w*v0.w
                    + v1.x*v1.x + v1.y*v1.y + v1.z*v1.z + v1.w*v1.w;
            #pragma unroll
            for (int off = 16; off > 0; off >>= 1)
                s += __shfl_xor_sync(0xFFFFFFFFu, s, off);
            if (lane == 0) g_e2[b] = s;
        }

    } else {
        // ----- decode prototype_valid (dtype-sniffing)
        __shared__ int s_hasF, s_hasHi, s_mode;
        if (tid == 0) { s_hasF = 0; s_hasHi = 0; }
        __syncthreads();
        if (tid < 128) {   // first 512 bytes — in-bounds for uint8/int32/float32
            unsigned v = ((const unsigned*)valid)[tid];
            if (v == 0x3F800000u)                        atomicOr(&s_hasF, 1);
            else if (v != 0u && (v & 0xFFFFFF00u) != 0u) atomicOr(&s_hasHi, 1);
        }
        __syncthreads();
        if (tid == 0) s_mode = s_hasF ? 0 : (s_hasHi ? 2 : 1);
        __syncthreads();
        const int mode = s_mode;
        for (int i = tid; i < CC * KK; i += 256) {
            bool v;
            if (mode == 0)      v = ((const float*)valid)[i] != 0.0f;
            else if (mode == 1) v = ((const int*)valid)[i] != 0;
            else                v = ((const unsigned char*)valid)[i] != 0;
            g_inval[i] = v ? 0.0f : -CUDART_INF_F;
        }
    }
}

// ===========================================================================
// Kernel B: dotep[b][ck] = emb[b,:]·proto[ck,:]  (tf32 mma)
// Block tile 64x64, BK=16 double-buffered, 128 thr (4 warps 2x2), warp 32x32.
// ===========================================================================
#define QW_BK 16
__global__ __launch_bounds__(128) void dotep_gemm_tf32(
    const float* __restrict__ emb, const float* __restrict__ protos)
{
    const int bn0 = blockIdx.x * 64;
    const int bm0 = blockIdx.y * 64;

    __shared__ __align__(16) float As[2][64][QW_BK + 4];
    __shared__ __align__(16) float Ps[2][64][QW_BK + 4];

    const int tid  = threadIdx.x;
    const int warp = tid >> 5, lane = tid & 31;
    const int wm = (warp >> 1) * 32;
    const int wn = (warp & 1) * 32;
    const int g  = lane >> 2, tg = lane & 3;

    float acc[2][4][4];
    #pragma unroll
    for (int i = 0; i < 2; ++i)
        #pragma unroll
        for (int j = 0; j < 4; ++j)
            #pragma unroll
            for (int t = 0; t < 4; ++t) acc[i][j][t] = 0.f;

    #define DE_LOAD(s, kbase)                                                        \
        {                                                                             \
            _Pragma("unroll")                                                         \
            for (int i_ = 0; i_ < 2; ++i_) {                                          \
                int slot = tid + i_ * 128;                                            \
                int m = slot >> 2, k4 = (slot & 3) << 2;                              \
                cp16(&As[s][m][k4], emb + (size_t)(bm0 + m) * DD + (kbase) + k4);     \
                cp16(&Ps[s][m][k4], protos + (size_t)(bn0 + m) * DD + (kbase) + k4);  \
            }                                                                         \
            CP_COMMIT();                                                              \
        }

    DE_LOAD(0, 0);
    int s = 0;
    const int NT = DD / QW_BK;
    for (int kt = 0; kt < NT; ++kt) {
        if (kt + 1 < NT) { DE_LOAD(s ^ 1, (kt + 1) * QW_BK); CP_WAIT(1); }
        else             { CP_WAIT(0); }
        __syncthreads();

        #pragma unroll
        for (int ks = 0; ks < 2; ++ks) {
            const int kb = ks * 8;
            uint32_t afr[2][4], bfr[4][2];
            #pragma unroll
            for (int i = 0; i < 2; ++i) {
                int m0 = wm + i * 16;
                afr[i][0] = f2tf(As[s][m0 + g][kb + tg]);
                afr[i][1] = f2tf(As[s][m0 + g + 8][kb + tg]);
                afr[i][2] = f2tf(As[s][m0 + g][kb + tg + 4]);
                afr[i][3] = f2tf(As[s][m0 + g + 8][kb + tg + 4]);
            }
            #pragma unroll
            for (int j = 0; j < 4; ++j) {
                int n0 = wn + j * 8;
                bfr[j][0] = f2tf(Ps[s][n0 + g][kb + tg]);
                bfr[j][1] = f2tf(Ps[s][n0 + g][kb + tg + 4]);
            }
            #pragma unroll
            for (int i = 0; i < 2; ++i)
                #pragma unroll
                for (int j = 0; j < 4; ++j)
                    mma_tf32(acc[i][j], afr[i], bfr[j]);
        }
        __syncthreads();
        s ^= 1;
    }

    #pragma unroll
    for (int i = 0; i < 2; ++i) {
        int r0 = bm0 + wm + i * 16 + g;
        #pragma unroll
        for (int j = 0; j < 4; ++j) {
            int col = bn0 + wn + j * 8 + 2 * tg;
            *(float2*)(g_dotep + (size_t)r0 * (CC * KK) + col)       = make_float2(acc[i][j][0], acc[i][j][1]);
            *(float2*)(g_dotep + (size_t)(r0 + 8) * (CC * KK) + col) = make_float2(acc[i][j][2], acc[i][j][3]);
        }
    }
    #undef DE_LOAD
}

// ===========================================================================
// Kernel C (main, fused): per (128-batch-tile, class):
//   1. qW tile [128 x 256] = emb_tile @ W1top  (tf32 mma, acc in registers)
//   2. epilogue: scores[b][k] = sum_d w2[d]*tanh(qW+pt[k][d])  (register acc)
//   3. softmax over K, dist via Gram trick, write out
// grid (8, 32), 256 threads (8 warps, 2m x 4n, warp tile 64x64).
// Dynamic smem: GEMM stage (As+Bs = 53.8 KB) aliased with epilogue tables.
// ===========================================================================
__global__ __launch_bounds__(256, 1) void fused_main(
    const float* __restrict__ emb, const float* __restrict__ W1,
    const float* __restrict__ w2, const float* __restrict__ b2,
    const float* __restrict__ temperature, float* __restrict__ out)
{
    extern __shared__ float sh[];
    // phase-1 layout
    float* Asb = sh;                       // [2][128][20]  = 5120 floats
    float* Bsb = sh + 2 * 128 * 20;        // [2][16][260]  = 8320 floats
    // phase-2 layout (aliases phase-1 region)
    float* sh_pt    = sh;                  // [16][256] = 4096
    float* sh_score = sh + 4096;           // [128][17] = 2176
    float* sh_w2    = sh + 4096 + 2176;    // 256
    float* sh_G     = sh_w2 + 256;         // [16][17] = 272
    float* sh_inval = sh_G + 272;          // 16

    const int c  = blockIdx.y;
    const int b0 = blockIdx.x * 128;
    const float* A  = emb;
    const float* Bm = W1 + (size_t)c * TWO_D * DD;   // top half [256 k][256 n]

    const int tid  = threadIdx.x;
    const int warp = tid >> 5, lane = tid & 31;
    const int wm = (warp >> 2) * 64;     // 0 or 64
    const int wn = (warp & 3) * 64;      // 0,64,128,192
    const int g  = lane >> 2, tg = lane & 3;

    float acc[4][8][4];
    #pragma unroll
    for (int i = 0; i < 4; ++i)
        #pragma unroll
        for (int j = 0; j < 8; ++j)
            #pragma unroll
            for (int t = 0; t < 4; ++t) acc[i][j][t] = 0.f;

    #define AS(s, m, k) Asb[(s) * 2560 + (m) * 20 + (k)]
    #define BS(s, k, n) Bsb[(s) * 4160 + (k) * 260 + (n)]
    #define FM_LOAD(s, kbase)                                                    \
        {                                                                         \
            _Pragma("unroll")                                                     \
            for (int i_ = 0; i_ < 2; ++i_) {                                      \
                int slot = tid + i_ * 256;                                        \
                int m = slot >> 2, k4 = (slot & 3) << 2;                          \
                cp16(&AS(s, m, k4), A + (size_t)(b0 + m) * DD + (kbase) + k4);    \
            }                                                                     \
            _Pragma("unroll")                                                     \
            for (int i_ = 0; i_ < 4; ++i_) {                                      \
                int slot = tid + i_ * 256;                                        \
                int k = slot >> 6, n4 = (slot & 63) << 2;                         \
                cp16(&BS(s, k, n4), Bm + (size_t)((kbase) + k) * DD + n4);        \
            }                                                                     \
            CP_COMMIT();                                                          \
        }

    // ---------------- Phase 1: tf32 GEMM ----------------
    FM_LOAD(0, 0);
    int s = 0;
    const int NT = DD / QW_BK;   // 16
    for (int kt = 0; kt < NT; ++kt) {
        if (kt + 1 < NT) { FM_LOAD(s ^ 1, (kt + 1) * QW_BK); CP_WAIT(1); }
        else             { CP_WAIT(0); }
        __syncthreads();

        #pragma unroll
        for (int ks = 0; ks < 2; ++ks) {
            const int kb = ks * 8;
            uint32_t afr[4][4], bfr[8][2];
            #pragma unroll
            for (int i = 0; i < 4; ++i) {
                int m0 = wm + i * 16;
                afr[i][0] = f2tf(AS(s, m0 + g,     kb + tg));
                afr[i][1] = f2tf(AS(s, m0 + g + 8, kb + tg));
                afr[i][2] = f2tf(AS(s, m0 + g,     kb + tg + 4));
                afr[i][3] = f2tf(AS(s, m0 + g + 8, kb + tg + 4));
            }
            #pragma unroll
            for (int j = 0; j < 8; ++j) {
                int n0 = wn + j * 8;
                bfr[j][0] = f2tf(BS(s, kb + tg,     n0 + g));
                bfr[j][1] = f2tf(BS(s, kb + tg + 4, n0 + g));
            }
            #pragma unroll
            for (int i = 0; i < 4; ++i)
                #pragma unroll
                for (int j = 0; j < 8; ++j)
                    mma_tf32(acc[i][j], afr[i], bfr[j]);
        }
        __syncthreads();
        s ^= 1;
    }
    // last iteration ended with __syncthreads() — safe to repurpose smem.

    // ---------------- Phase 2 tables ----------------
    {
        const float* ptg = g_proto_term + (size_t)c * KK * DD;
        for (int i = tid; i < KK * DD; i += 256) sh_pt[i] = ptg[i];
        for (int i = tid; i < 128 * 17; i += 256) sh_score[i] = 0.f;
        if (tid < DD) sh_w2[tid] = w2[c * DD + tid];
        if (tid < KK * KK) sh_G[(tid >> 4) * 17 + (tid & 15)] = g_G[c * 256 + tid];
        if (tid < KK) sh_inval[tid] = g_inval[c * KK + tid];
    }
    __syncthreads();

    // per-thread w2 values for held columns
    float2 w2v[8];
    #pragma unroll
    for (int j = 0; j < 8; ++j)
        w2v[j] = *(float2*)&sh_w2[wn + j * 8 + 2 * tg];

    // ---------------- Phase 3: tanh scores ----------------
    #pragma unroll 1
    for (int k = 0; k < KK; ++k) {
        float2 ptv[8];
        #pragma unroll
        for (int j = 0; j < 8; ++j)
            ptv[j] = *(float2*)&sh_pt[k * DD + wn + j * 8 + 2 * tg];

        float part[8];
        #pragma unroll
        for (int i = 0; i < 4; ++i) {
            float p0 = 0.f, p1 = 0.f;
            #pragma unroll
            for (int j = 0; j < 8; ++j) {
                p0 = fmaf(w2v[j].x, tanh_fast(acc[i][j][0] + ptv[j].x), p0);
                p0 = fmaf(w2v[j].y, tanh_fast(acc[i][j][1] + ptv[j].y), p0);
                p1 = fmaf(w2v[j].x, tanh_fast(acc[i][j][2] + ptv[j].x), p1);
                p1 = fmaf(w2v[j].y, tanh_fast(acc[i][j][3] + ptv[j].y), p1);
            }
            part[2 * i]     = p0;
            part[2 * i + 1] = p1;
        }
        // reduce over tg (lane bits 0..1): 4 lanes hold same row-quarter
        #pragma unroll
        for (int r = 0; r < 8; ++r) {
            part[r] += __shfl_xor_sync(0xFFFFFFFFu, part[r], 1);
            part[r] += __shfl_xor_sync(0xFFFFFFFFu, part[r], 2);
        }
        if (tg == 0) {
            #pragma unroll
            for (int r = 0; r < 8; ++r) {
                int row = wm + (r >> 1) * 16 + g + ((r & 1) << 3);
                atomicAdd(&sh_score[row * 17 + k], part[r]);
            }
        }
    }
    __syncthreads();

    // ---------------- Phase 4: softmax + Gram distance ----------------
    if (tid < 128) {
        const int b = b0 + tid;
        const float b2v  = b2[c];
        const float temp = temperature[0];

        float s16[KK];
        #pragma unroll
        for (int k = 0; k < KK; ++k)
            s16[k] = sh_score[tid * 17 + k] + b2v + sh_inval[k];

        float m = s16[0];
        #pragma unroll
        for (int k = 1; k < KK; ++k) m = fmaxf(m, s16[k]);
        float sum = 0.f;
        #pragma unroll
        for (int k = 0; k < KK; ++k) {
            float e = __expf(s16[k] - m);
            s16[k] = e;
            sum += e;
        }
        float inv = 1.f / sum;
        #pragma unroll
        for (int k = 0; k < KK; ++k) s16[k] *= inv;

        // dist^2 = e2 - 2*attn·dotep + attn^T G attn
        float depv[KK];
        const float4* dep = (const float4*)(g_dotep + (size_t)b * (CC * KK) + c * KK);
        #pragma unroll
        for (int q = 0; q < 4; ++q) {
            float4 v = dep[q];
            depv[4 * q + 0] = v.x; depv[4 * q + 1] = v.y;
            depv[4 * q + 2] = v.z; depv[4 * q + 3] = v.w;
        }
        float dist2 = g_e2[b];
        #pragma unroll
        for (int k = 0; k < KK; ++k)
            dist2 = fmaf(-2.0f * s16[k], depv[k], dist2);
        #pragma unroll
        for (int k = 0; k < KK; ++k) {
            float t = 0.f;
            #pragma unroll
            for (int k2 = 0; k2 < KK; ++k2)
                t = fmaf(sh_G[k * 17 + k2], s16[k2], t);
            dist2 = fmaf(s16[k], t, dist2);
        }
        out[(size_t)b * CC + c] = -sqrtf(fmaxf(dist2, 0.f)) * temp;
    }
    #undef AS
    #undef BS
    #undef FM_LOAD
}

// ---------------------------------------------------------------------------
extern "C" void kernel_launch(void* const* d_in, const int* in_sizes, int n_in,
                              void* d_out, int out_size)
{
    const float* emb    = (const float*)d_in[0];   // [B,D]
    const float* protos = (const float*)d_in[1];   // [C,K,D]
    const float* W1     = (const float*)d_in[2];   // [C,2D,D]
    const float* b1     = (const float*)d_in[3];   // [C,D]
    const float* w2     = (const float*)d_in[4];   // [C,D]
    const float* b2     = (const float*)d_in[5];   // [C]
    const float* temp   = (const float*)d_in[6];   // [1]
    const void*  valid  = (const void*)d_in[7];    // [C,K] bool (storage dtype unknown)
    float* out = (float*)d_out;                    // [B,C]

    const int dyn = (2 * 128 * 20 + 2 * 16 * 260) * 4;   // 53760 bytes
    cudaFuncSetAttribute(fused_main, cudaFuncAttributeMaxDynamicSharedMemorySize, dyn);

    prologue_kernel<<<129, 256>>>(emb, protos, W1, b1, valid);
    dotep_gemm_tf32<<<dim3(8, 16), 128>>>(emb, protos);
    fused_main<<<dim3(8, CC), 256, dyn>>>(emb, W1, w2, b2, temp, out);
}

// round 5
// speedup vs baseline: 1.7276x; 1.1631x over previous
#include <cuda_runtime.h>
#include <math_constants.h>
#include <cstdint>

// Problem constants
#define BB 1024   // batch
#define CC 32     // classes
#define KK 16     // prototypes per class
#define DD 256    // embedding dim
#define TWO_D 512

// Scratch (static device arrays — no allocation allowed)
__device__ float g_proto_term[CC * KK * DD];          // 512 KB
__device__ float g_dotep[(size_t)BB * CC * KK];       // 2 MB: emb·proto
__device__ float g_G[CC * KK * KK];                   // 32 KB: Gram
__device__ float g_e2[BB];                            // |emb|^2
__device__ float g_inval[CC * KK];                    // 0 = valid, -inf = invalid

__device__ __forceinline__ float tanh_fast(float x) {
    float r;
    asm("tanh.approx.f32 %0, %1;" : "=f"(r) : "f"(x));
    return r;
}
__device__ __forceinline__ uint32_t f2tf(float f) {
    uint32_t r;
    asm("cvt.rna.tf32.f32 %0, %1;" : "=r"(r) : "f"(f));
    return r;
}
__device__ __forceinline__ void cp16(void* smem, const void* g) {
    uint32_t sa = (uint32_t)__cvta_generic_to_shared(smem);
    asm volatile("cp.async.cg.shared.global [%0], [%1], 16;" :: "r"(sa), "l"(g));
}
#define CP_COMMIT() asm volatile("cp.async.commit_group;")
#define CP_WAIT(N)  asm volatile("cp.async.wait_group %0;" :: "n"(N))

__device__ __forceinline__ void mma_tf32(float c_[4], const uint32_t a[4], const uint32_t b[2]) {
    asm volatile(
        "mma.sync.aligned.m16n8k8.row.col.f32.tf32.tf32.f32 "
        "{%0,%1,%2,%3}, {%4,%5,%6,%7}, {%8,%9}, {%0,%1,%2,%3};"
        : "+f"(c_[0]), "+f"(c_[1]), "+f"(c_[2]), "+f"(c_[3])
        : "r"(a[0]), "r"(a[1]), "r"(a[2]), "r"(a[3]), "r"(b[0]), "r"(b[1]));
}

// ===========================================================================
// Kernel A (prologue, fused): blockIdx dispatch
//   blocks [0,128)   : proto_term  (c = blk>>2, d-slice = (blk&3)*64)
//                      each block: all 16 protos x 64 d-columns; e-reduction
//                      split over 4 thread-groups of 64 e's, smem reduce.
//   blocks [128,160) : Gram        (c = blk-128)
//   blocks [160,192) : e2          (32 rows per block, warp-per-row x4)
//   block  192       : decode prototype_valid mask
// ===========================================================================
__global__ __launch_bounds__(256) void prologue_kernel(
    const float* __restrict__ emb,      // [B,D]
    const float* __restrict__ protos,   // [C,K,D]
    const float* __restrict__ W1,       // [C,2D,D]
    const float* __restrict__ b1,       // [C,D]
    const void*  __restrict__ valid)
{
    __shared__ float sh[KK * DD + 4 * KK * 64];   // 16 KB protos + 16 KB reduce = 32 KB
    const int blk = blockIdx.x;
    const int tid = threadIdx.x;

    if (blk < 128) {
        // ----- proto_term[c][k][d0+dl] = b1 + sum_e protos[c][k][e]*W1[c][D+e][d0+dl]
        const int c  = blk >> 2;
        const int d0 = (blk & 3) * 64;
        const int dl = tid & 63;        // d within slice
        const int eg = tid >> 6;        // e-group 0..3 (64 e's each)

        float* p_s  = sh;               // [16][256]
        float* sred = sh + KK * DD;     // [4][16][64]

        // cooperative load of all 16 prototypes (coalesced, 16 floats/thread)
        const float* pg = protos + (size_t)c * KK * DD;
        #pragma unroll
        for (int i = 0; i < 16; ++i) p_s[tid + i * 256] = pg[tid + i * 256];
        __syncthreads();

        float acc[KK];
        #pragma unroll
        for (int k = 0; k < KK; ++k) acc[k] = 0.f;

        // W1 bottom: rows D+eg*64 .. D+eg*64+63, column d0+dl
        const float* Wb = W1 + ((size_t)c * TWO_D + DD + eg * 64) * DD + d0 + dl;
        #pragma unroll 4
        for (int e = 0; e < 64; ++e) {
            float w = Wb[(size_t)e * DD];          // coalesced over dl
            const float* pe = p_s + eg * 64 + e;   // protos[k][eg*64+e]
            #pragma unroll
            for (int k = 0; k < KK; ++k)
                acc[k] = fmaf(pe[k * DD], w, acc[k]);
        }

        // write partials, reduce over eg
        #pragma unroll
        for (int k = 0; k < KK; ++k)
            sred[(eg * KK + k) * 64 + dl] = acc[k];
        __syncthreads();

        // 256 threads cover 16k x 64d = 1024 outputs, 4 each
        #pragma unroll
        for (int r = 0; r < 4; ++r) {
            int idx = tid + r * 256;        // k*64 + dl
            int k = idx >> 6, d = idx & 63;
            float s = sred[(0 * KK + k) * 64 + d] + sred[(1 * KK + k) * 64 + d]
                    + sred[(2 * KK + k) * 64 + d] + sred[(3 * KK + k) * 64 + d];
            g_proto_term[((c * KK) + k) * DD + d0 + d] = s + b1[c * DD + d0 + d];
        }

    } else if (blk < 160) {
        // ----- Gram G[c][k][k2]
        const int c = blk - 128;
        float* p_s = sh;   // [16][257]
        for (int i = tid; i < KK * DD; i += 256) {
            int k = i / DD, d = i % DD;
            p_s[k * (DD + 1) + d] = protos[(size_t)c * KK * DD + i];
        }
        __syncthreads();
        const int k = tid >> 4, k2 = tid & 15;
        float s = 0.f;
        #pragma unroll 4
        for (int d = 0; d < DD; ++d)
            s = fmaf(p_s[k * (DD + 1) + d], p_s[k2 * (DD + 1) + d], s);
        g_G[c * 256 + tid] = s;

    } else if (blk < 192) {
        // ----- e2: warp-per-row, 4 rows per warp
        const int warp = tid >> 5, lane = tid & 31;
        const int base = (blk - 160) * 32 + warp * 4;
        #pragma unroll
        for (int t = 0; t < 4; ++t) {
            const int b = base + t;
            const float4* p = (const float4*)(emb + (size_t)b * DD);
            float4 v0 = p[lane], v1 = p[lane + 32];
            float s = v0.x*v0.x + v0.y*v0.y + v0.z*v0.z + v0.w*v0.w
                    + v1.x*v1.x + v1.y*v1.y + v1.z*v1.z + v1.w*v1.w;
            #pragma unroll
            for (int off = 16; off > 0; off >>= 1)
                s += __shfl_xor_sync(0xFFFFFFFFu, s, off);
            if (lane == 0) g_e2[b] = s;
        }

    } else {
        // ----- decode prototype_valid (dtype-sniffing)
        __shared__ int s_hasF, s_hasHi, s_mode;
        if (tid == 0) { s_hasF = 0; s_hasHi = 0; }
        __syncthreads();
        if (tid < 128) {   // first 512 bytes — in-bounds for uint8/int32/float32
            unsigned v = ((const unsigned*)valid)[tid];
            if (v == 0x3F800000u)                        atomicOr(&s_hasF, 1);
            else if (v != 0u && (v & 0xFFFFFF00u) != 0u) atomicOr(&s_hasHi, 1);
        }
        __syncthreads();
        if (tid == 0) s_mode = s_hasF ? 0 : (s_hasHi ? 2 : 1);
        __syncthreads();
        const int mode = s_mode;
        for (int i = tid; i < CC * KK; i += 256) {
            bool v;
            if (mode == 0)      v = ((const float*)valid)[i] != 0.0f;
            else if (mode == 1) v = ((const int*)valid)[i] != 0;
            else                v = ((const unsigned char*)valid)[i] != 0;
            g_inval[i] = v ? 0.0f : -CUDART_INF_F;
        }
    }
}

// ===========================================================================
// Kernel B: dotep[b][ck] = emb[b,:]·proto[ck,:]  (tf32 mma)
// Block tile 64x64, BK=16 double-buffered, 128 thr (4 warps 2x2), warp 32x32.
// ===========================================================================
#define QW_BK 16
__global__ __launch_bounds__(128) void dotep_gemm_tf32(
    const float* __restrict__ emb, const float* __restrict__ protos)
{
    const int bn0 = blockIdx.x * 64;
    const int bm0 = blockIdx.y * 64;

    __shared__ __align__(16) float As[2][64][QW_BK + 4];
    __shared__ __align__(16) float Ps[2][64][QW_BK + 4];

    const int tid  = threadIdx.x;
    const int warp = tid >> 5, lane = tid & 31;
    const int wm = (warp >> 1) * 32;
    const int wn = (warp & 1) * 32;
    const int g  = lane >> 2, tg = lane & 3;

    float acc[2][4][4];
    #pragma unroll
    for (int i = 0; i < 2; ++i)
        #pragma unroll
        for (int j = 0; j < 4; ++j)
            #pragma unroll
            for (int t = 0; t < 4; ++t) acc[i][j][t] = 0.f;

    #define DE_LOAD(s, kbase)                                                        \
        {                                                                             \
            _Pragma("unroll")                                                         \
            for (int i_ = 0; i_ < 2; ++i_) {                                          \
                int slot = tid + i_ * 128;                                            \
                int m = slot >> 2, k4 = (slot & 3) << 2;                              \
                cp16(&As[s][m][k4], emb + (size_t)(bm0 + m) * DD + (kbase) + k4);     \
                cp16(&Ps[s][m][k4], protos + (size_t)(bn0 + m) * DD + (kbase) + k4);  \
            }                                                                         \
            CP_COMMIT();                                                              \
        }

    DE_LOAD(0, 0);
    int s = 0;
    const int NT = DD / QW_BK;
    for (int kt = 0; kt < NT; ++kt) {
        if (kt + 1 < NT) { DE_LOAD(s ^ 1, (kt + 1) * QW_BK); CP_WAIT(1); }
        else             { CP_WAIT(0); }
        __syncthreads();

        #pragma unroll
        for (int ks = 0; ks < 2; ++ks) {
            const int kb = ks * 8;
            uint32_t afr[2][4], bfr[4][2];
            #pragma unroll
            for (int i = 0; i < 2; ++i) {
                int m0 = wm + i * 16;
                afr[i][0] = f2tf(As[s][m0 + g][kb + tg]);
                afr[i][1] = f2tf(As[s][m0 + g + 8][kb + tg]);
                afr[i][2] = f2tf(As[s][m0 + g][kb + tg + 4]);
                afr[i][3] = f2tf(As[s][m0 + g + 8][kb + tg + 4]);
            }
            #pragma unroll
            for (int j = 0; j < 4; ++j) {
                int n0 = wn + j * 8;
                bfr[j][0] = f2tf(Ps[s][n0 + g][kb + tg]);
                bfr[j][1] = f2tf(Ps[s][n0 + g][kb + tg + 4]);
            }
            #pragma unroll
            for (int i = 0; i < 2; ++i)
                #pragma unroll
                for (int j = 0; j < 4; ++j)
                    mma_tf32(acc[i][j], afr[i], bfr[j]);
        }
        __syncthreads();
        s ^= 1;
    }

    #pragma unroll
    for (int i = 0; i < 2; ++i) {
        int r0 = bm0 + wm + i * 16 + g;
        #pragma unroll
        for (int j = 0; j < 4; ++j) {
            int col = bn0 + wn + j * 8 + 2 * tg;
            *(float2*)(g_dotep + (size_t)r0 * (CC * KK) + col)       = make_float2(acc[i][j][0], acc[i][j][1]);
            *(float2*)(g_dotep + (size_t)(r0 + 8) * (CC * KK) + col) = make_float2(acc[i][j][2], acc[i][j][3]);
        }
    }
    #undef DE_LOAD
}

// ===========================================================================
// Kernel C (main, fused): per (128-batch-tile, class):
//   1. qW tile [128 x 256] = emb_tile @ W1top  (tf32 mma, acc in registers)
//   2. epilogue: scores[b][k] = sum_d w2[d]*tanh(qW+pt[k][d])  (register acc)
//   3. softmax over K, dist via Gram trick, write out
// grid (8, 32), 256 threads (8 warps, 2m x 4n, warp tile 64x64).
// Dynamic smem: GEMM stage (As+Bs = 53.8 KB) aliased with epilogue tables.
// ===========================================================================
__global__ __launch_bounds__(256, 1) void fused_main(
    const float* __restrict__ emb, const float* __restrict__ W1,
    const float* __restrict__ w2, const float* __restrict__ b2,
    const float* __restrict__ temperature, float* __restrict__ out)
{
    extern __shared__ float sh[];
    // phase-1 layout
    float* Asb = sh;                       // [2][128][20]  = 5120 floats
    float* Bsb = sh + 2 * 128 * 20;        // [2][16][260]  = 8320 floats
    // phase-2 layout (aliases phase-1 region)
    float* sh_pt    = sh;                  // [16][256] = 4096
    float* sh_score = sh + 4096;           // [128][17] = 2176
    float* sh_w2    = sh + 4096 + 2176;    // 256
    float* sh_G     = sh_w2 + 256;         // [16][17] = 272
    float* sh_inval = sh_G + 272;          // 16

    const int c  = blockIdx.y;
    const int b0 = blockIdx.x * 128;
    const float* A  = emb;
    const float* Bm = W1 + (size_t)c * TWO_D * DD;   // top half [256 k][256 n]

    const int tid  = threadIdx.x;
    const int warp = tid >> 5, lane = tid & 31;
    const int wm = (warp >> 2) * 64;     // 0 or 64
    const int wn = (warp & 3) * 64;      // 0,64,128,192
    const int g  = lane >> 2, tg = lane & 3;

    float acc[4][8][4];
    #pragma unroll
    for (int i = 0; i < 4; ++i)
        #pragma unroll
        for (int j = 0; j < 8; ++j)
            #pragma unroll
            for (int t = 0; t < 4; ++t) acc[i][j][t] = 0.f;

    #define AS(s, m, k) Asb[(s) * 2560 + (m) * 20 + (k)]
    #define BS(s, k, n) Bsb[(s) * 4160 + (k) * 260 + (n)]
    #define FM_LOAD(s, kbase)                                                    \
        {                                                                         \
            _Pragma("unroll")                                                     \
            for (int i_ = 0; i_ < 2; ++i_) {                                      \
                int slot = tid + i_ * 256;                                        \
                int m = slot >> 2, k4 = (slot & 3) << 2;                          \
                cp16(&AS(s, m, k4), A + (size_t)(b0 + m) * DD + (kbase) + k4);    \
            }                                                                     \
            _Pragma("unroll")                                                     \
            for (int i_ = 0; i_ < 4; ++i_) {                                      \
                int slot = tid + i_ * 256;                                        \
                int k = slot >> 6, n4 = (slot & 63) << 2;                         \
                cp16(&BS(s, k, n4), Bm + (size_t)((kbase) + k) * DD + n4);        \
            }                                                                     \
            CP_COMMIT();                                                          \
        }

    // ---------------- Phase 1: tf32 GEMM ----------------
    FM_LOAD(0, 0);
    int s = 0;
    const int NT = DD / QW_BK;   // 16
    for (int kt = 0; kt < NT; ++kt) {
        if (kt + 1 < NT) { FM_LOAD(s ^ 1, (kt + 1) * QW_BK); CP_WAIT(1); }
        else             { CP_WAIT(0); }
        __syncthreads();

        #pragma unroll
        for (int ks = 0; ks < 2; ++ks) {
            const int kb = ks * 8;
            uint32_t afr[4][4], bfr[8][2];
            #pragma unroll
            for (int i = 0; i < 4; ++i) {
                int m0 = wm + i * 16;
                afr[i][0] = f2tf(AS(s, m0 + g,     kb + tg));
                afr[i][1] = f2tf(AS(s, m0 + g + 8, kb + tg));
                afr[i][2] = f2tf(AS(s, m0 + g,     kb + tg + 4));
                afr[i][3] = f2tf(AS(s, m0 + g + 8, kb + tg + 4));
            }
            #pragma unroll
            for (int j = 0; j < 8; ++j) {
                int n0 = wn + j * 8;
                bfr[j][0] = f2tf(BS(s, kb + tg,     n0 + g));
                bfr[j][1] = f2tf(BS(s, kb + tg + 4, n0 + g));
            }
            #pragma unroll
            for (int i = 0; i < 4; ++i)
                #pragma unroll
                for (int j = 0; j < 8; ++j)
                    mma_tf32(acc[i][j], afr[i], bfr[j]);
        }
        __syncthreads();
        s ^= 1;
    }
    // last iteration ended with __syncthreads() — safe to repurpose smem.

    // ---------------- Phase 2 tables ----------------
    {
        const float* ptg = g_proto_term + (size_t)c * KK * DD;
        for (int i = tid; i < KK * DD; i += 256) sh_pt[i] = ptg[i];
        for (int i = tid; i < 128 * 17; i += 256) sh_score[i] = 0.f;
        if (tid < DD) sh_w2[tid] = w2[c * DD + tid];
        if (tid < KK * KK) sh_G[(tid >> 4) * 17 + (tid & 15)] = g_G[c * 256 + tid];
        if (tid < KK) sh_inval[tid] = g_inval[c * KK + tid];
    }
    __syncthreads();

    // per-thread w2 values for held columns
    float2 w2v[8];
    #pragma unroll
    for (int j = 0; j < 8; ++j)
        w2v[j] = *(float2*)&sh_w2[wn + j * 8 + 2 * tg];

    // ---------------- Phase 3: tanh scores ----------------
    #pragma unroll 1
    for (int k = 0; k < KK; ++k) {
        float2 ptv[8];
        #pragma unroll
        for (int j = 0; j < 8; ++j)
            ptv[j] = *(float2*)&sh_pt[k * DD + wn + j * 8 + 2 * tg];

        float part[8];
        #pragma unroll
        for (int i = 0; i < 4; ++i) {
            float p0 = 0.f, p1 = 0.f;
            #pragma unroll
            for (int j = 0; j < 8; ++j) {
                p0 = fmaf(w2v[j].x, tanh_fast(acc[i][j][0] + ptv[j].x), p0);
                p0 = fmaf(w2v[j].y, tanh_fast(acc[i][j][1] + ptv[j].y), p0);
                p1 = fmaf(w2v[j].x, tanh_fast(acc[i][j][2] + ptv[j].x), p1);
                p1 = fmaf(w2v[j].y, tanh_fast(acc[i][j][3] + ptv[j].y), p1);
            }
            part[2 * i]     = p0;
            part[2 * i + 1] = p1;
        }
        // reduce over tg (lane bits 0..1): 4 lanes hold same row-quarter
        #pragma unroll
        for (int r = 0; r < 8; ++r) {
            part[r] += __shfl_xor_sync(0xFFFFFFFFu, part[r], 1);
            part[r] += __shfl_xor_sync(0xFFFFFFFFu, part[r], 2);
        }
        if (tg == 0) {
            #pragma unroll
            for (int r = 0; r < 8; ++r) {
                int row = wm + (r >> 1) * 16 + g + ((r & 1) << 3);
                atomicAdd(&sh_score[row * 17 + k], part[r]);
            }
        }
    }
    __syncthreads();

    // ---------------- Phase 4: softmax + Gram distance ----------------
    if (tid < 128) {
        const int b = b0 + tid;
        const float b2v  = b2[c];
        const float temp = temperature[0];

        float s16[KK];
        #pragma unroll
        for (int k = 0; k < KK; ++k)
            s16[k] = sh_score[tid * 17 + k] + b2v + sh_inval[k];

        float m = s16[0];
        #pragma unroll
        for (int k = 1; k < KK; ++k) m = fmaxf(m, s16[k]);
        float sum = 0.f;
        #pragma unroll
        for (int k = 0; k < KK; ++k) {
            float e = __expf(s16[k] - m);
            s16[k] = e;
            sum += e;
        }
        float inv = 1.f / sum;
        #pragma unroll
        for (int k = 0; k < KK; ++k) s16[k] *= inv;

        // dist^2 = e2 - 2*attn·dotep + attn^T G attn
        float depv[KK];
        const float4* dep = (const float4*)(g_dotep + (size_t)b * (CC * KK) + c * KK);
        #pragma unroll
        for (int q = 0; q < 4; ++q) {
            float4 v = dep[q];
            depv[4 * q + 0] = v.x; depv[4 * q + 1] = v.y;
            depv[4 * q + 2] = v.z; depv[4 * q + 3] = v.w;
        }
        float dist2 = g_e2[b];
        #pragma unroll
        for (int k = 0; k < KK; ++k)
            dist2 = fmaf(-2.0f * s16[k], depv[k], dist2);
        #pragma unroll
        for (int k = 0; k < KK; ++k) {
            float t = 0.f;
            #pragma unroll
            for (int k2 = 0; k2 < KK; ++k2)
                t = fmaf(sh_G[k * 17 + k2], s16[k2], t);
            dist2 = fmaf(s16[k], t, dist2);
        }
        out[(size_t)b * CC + c] = -sqrtf(fmaxf(dist2, 0.f)) * temp;
    }
    #undef AS
    #undef BS
    #undef FM_LOAD
}

// ---------------------------------------------------------------------------
extern "C" void kernel_launch(void* const* d_in, const int* in_sizes, int n_in,
                              void* d_out, int out_size)
{
    const float* emb    = (const float*)d_in[0];   // [B,D]
    const float* protos = (const float*)d_in[1];   // [C,K,D]
    const float* W1     = (const float*)d_in[2];   // [C,2D,D]
    const float* b1     = (const float*)d_in[3];   // [C,D]
    const float* w2     = (const float*)d_in[4];   // [C,D]
    const float* b2     = (const float*)d_in[5];   // [C]
    const float* temp   = (const float*)d_in[6];   // [1]
    const void*  valid  = (const void*)d_in[7];    // [C,K] bool (storage dtype unknown)
    float* out = (float*)d_out;                    // [B,C]

    const int dyn = (2 * 128 * 20 + 2 * 16 * 260) * 4;   // 53760 bytes
    cudaFuncSetAttribute(fused_main, cudaFuncAttributeMaxDynamicSharedMemorySize, dyn);

    prologue_kernel<<<193, 256>>>(emb, protos, W1, b1, valid);
    dotep_gemm_tf32<<<dim3(8, 16), 128>>>(emb, protos);
    fused_main<<<dim3(8, CC), 256, dyn>>>(emb, W1, w2, b2, temp, out);
}

// round 6
// speedup vs baseline: 2.0149x; 1.1663x over previous
#include <cuda_runtime.h>
#include <math_constants.h>
#include <cstdint>

// Problem constants
#define BB 1024   // batch
#define CC 32     // classes
#define KK 16     // prototypes per class
#define DD 256    // embedding dim
#define TWO_D 512

// Scratch (static device arrays — no allocation allowed)
__device__ float g_proto_term[CC * KK * DD];          // 512 KB
__device__ float g_dotep[(size_t)BB * CC * KK];       // 2 MB: emb·proto
__device__ float g_G[CC * KK * KK];                   // 32 KB: Gram
__device__ float g_e2[BB];                            // |emb|^2
__device__ float g_inval[CC * KK];                    // 0 = valid, -inf = invalid

__device__ __forceinline__ float tanh_fast(float x) {
    float r;
    asm("tanh.approx.f32 %0, %1;" : "=f"(r) : "f"(x));
    return r;
}
__device__ __forceinline__ uint32_t f2tf(float f) {
    uint32_t r;
    asm("cvt.rna.tf32.f32 %0, %1;" : "=r"(r) : "f"(f));
    return r;
}
__device__ __forceinline__ void cp16(void* smem, const void* g) {
    uint32_t sa = (uint32_t)__cvta_generic_to_shared(smem);
    asm volatile("cp.async.cg.shared.global [%0], [%1], 16;" :: "r"(sa), "l"(g));
}
#define CP_COMMIT() asm volatile("cp.async.commit_group;")
#define CP_WAIT(N)  asm volatile("cp.async.wait_group %0;" :: "n"(N))

__device__ __forceinline__ void mma_tf32(float c_[4], const uint32_t a[4], const uint32_t b[2]) {
    asm volatile(
        "mma.sync.aligned.m16n8k8.row.col.f32.tf32.tf32.f32 "
        "{%0,%1,%2,%3}, {%4,%5,%6,%7}, {%8,%9}, {%0,%1,%2,%3};"
        : "+f"(c_[0]), "+f"(c_[1]), "+f"(c_[2]), "+f"(c_[3])
        : "r"(a[0]), "r"(a[1]), "r"(a[2]), "r"(a[3]), "r"(b[0]), "r"(b[1]));
}

// ===========================================================================
// Kernel A (prologue, fused): blockIdx dispatch, 256 threads everywhere
//   [0,128)   : proto_term  (c = blk>>2, d-slice = (blk&3)*64), MLP-8 prefetch
//   [128,160) : Gram        (c = blk-128)
//   [160,192) : e2          (32 rows per block, warp-per-row x4)
//   192       : decode prototype_valid mask
//   [193,257) : dotep tf32 GEMM (64x128 tiles: bm0=(b>>2)*64, bn0=(b&3)*128)
// ===========================================================================
__global__ __launch_bounds__(256) void prologue_kernel(
    const float* __restrict__ emb,      // [B,D]
    const float* __restrict__ protos,   // [C,K,D]
    const float* __restrict__ W1,       // [C,2D,D]
    const float* __restrict__ b1,       // [C,D]
    const void*  __restrict__ valid)
{
    __shared__ __align__(16) float sh[8192];   // 32 KB, reused per role
    const int blk = blockIdx.x;
    const int tid = threadIdx.x;

    if (blk < 128) {
        // ----- proto_term[c][k][d0+dl] = b1 + sum_e protos[c][k][e]*W1[c][D+e][d0+dl]
        const int c  = blk >> 2;
        const int d0 = (blk & 3) * 64;
        const int dl = tid & 63;        // d within slice
        const int eg = tid >> 6;        // e-group 0..3 (64 e's each)

        float* p_s  = sh;               // [16][256]
        float* sred = sh + KK * DD;     // [4][16][64]

        const float* pg = protos + (size_t)c * KK * DD;
        #pragma unroll
        for (int i = 0; i < 16; ++i) p_s[tid + i * 256] = pg[tid + i * 256];
        __syncthreads();

        float acc[KK];
        #pragma unroll
        for (int k = 0; k < KK; ++k) acc[k] = 0.f;

        // W1 bottom rows D+eg*64 .. +63, column d0+dl; 8-deep prefetch (MLP=8)
        const float* Wb = W1 + ((size_t)c * TWO_D + DD + eg * 64) * DD + d0 + dl;
        for (int e0 = 0; e0 < 64; e0 += 8) {
            float w[8];
            #pragma unroll
            for (int u = 0; u < 8; ++u) w[u] = Wb[(size_t)(e0 + u) * DD];
            #pragma unroll
            for (int u = 0; u < 8; ++u) {
                const float* pe = p_s + eg * 64 + e0 + u;
                #pragma unroll
                for (int k = 0; k < KK; ++k)
                    acc[k] = fmaf(pe[k * DD], w[u], acc[k]);
            }
        }

        #pragma unroll
        for (int k = 0; k < KK; ++k)
            sred[(eg * KK + k) * 64 + dl] = acc[k];
        __syncthreads();

        #pragma unroll
        for (int r = 0; r < 4; ++r) {
            int idx = tid + r * 256;        // k*64 + dl
            int k = idx >> 6, d = idx & 63;
            float s = sred[(0 * KK + k) * 64 + d] + sred[(1 * KK + k) * 64 + d]
                    + sred[(2 * KK + k) * 64 + d] + sred[(3 * KK + k) * 64 + d];
            g_proto_term[((c * KK) + k) * DD + d0 + d] = s + b1[c * DD + d0 + d];
        }

    } else if (blk < 160) {
        // ----- Gram G[c][k][k2]
        const int c = blk - 128;
        float* p_s = sh;   // [16][257]
        for (int i = tid; i < KK * DD; i += 256) {
            int k = i / DD, d = i % DD;
            p_s[k * (DD + 1) + d] = protos[(size_t)c * KK * DD + i];
        }
        __syncthreads();
        const int k = tid >> 4, k2 = tid & 15;
        float s = 0.f;
        #pragma unroll 4
        for (int d = 0; d < DD; ++d)
            s = fmaf(p_s[k * (DD + 1) + d], p_s[k2 * (DD + 1) + d], s);
        g_G[c * 256 + tid] = s;

    } else if (blk < 192) {
        // ----- e2: warp-per-row, 4 rows per warp
        const int warp = tid >> 5, lane = tid & 31;
        const int base = (blk - 160) * 32 + warp * 4;
        #pragma unroll
        for (int t = 0; t < 4; ++t) {
            const int b = base + t;
            const float4* p = (const float4*)(emb + (size_t)b * DD);
            float4 v0 = p[lane], v1 = p[lane + 32];
            float s = v0.x*v0.x + v0.y*v0.y + v0.z*v0.z + v0.w*v0.w
                    + v1.x*v1.x + v1.y*v1.y + v1.z*v1.z + v1.w*v1.w;
            #pragma unroll
            for (int off = 16; off > 0; off >>= 1)
                s += __shfl_xor_sync(0xFFFFFFFFu, s, off);
            if (lane == 0) g_e2[b] = s;
        }

    } else if (blk == 192) {
        // ----- decode prototype_valid (dtype-sniffing)
        __shared__ int s_hasF, s_hasHi, s_mode;
        if (tid == 0) { s_hasF = 0; s_hasHi = 0; }
        __syncthreads();
        if (tid < 128) {   // first 512 bytes — in-bounds for uint8/int32/float32
            unsigned v = ((const unsigned*)valid)[tid];
            if (v == 0x3F800000u)                        atomicOr(&s_hasF, 1);
            else if (v != 0u && (v & 0xFFFFFF00u) != 0u) atomicOr(&s_hasHi, 1);
        }
        __syncthreads();
        if (tid == 0) s_mode = s_hasF ? 0 : (s_hasHi ? 2 : 1);
        __syncthreads();
        const int mode = s_mode;
        for (int i = tid; i < CC * KK; i += 256) {
            bool v;
            if (mode == 0)      v = ((const float*)valid)[i] != 0.0f;
            else if (mode == 1) v = ((const int*)valid)[i] != 0;
            else                v = ((const unsigned char*)valid)[i] != 0;
            g_inval[i] = v ? 0.0f : -CUDART_INF_F;
        }

    } else {
        // ----- dotep[b][ck] = emb[b,:]·proto[ck,:]  (tf32 mma)
        // 64x128 tile, BK=16 double-buffered, 8 warps (2m x 4n), warp 32x32.
        const int b    = blk - 193;              // 0..63
        const int bm0  = (b >> 2) * 64;          // over 1024 batch
        const int bn0  = (b & 3) * 128;          // over 512 protos

        // As [2][64][20] at sh[0], Ps [2][128][20] at sh[2560]
        #define DAS(s, m, k) sh[(s) * 1280 + (m) * 20 + (k)]
        #define DPS(s, n, k) sh[2560 + (s) * 2560 + (n) * 20 + (k)]

        const int warp = tid >> 5, lane = tid & 31;
        const int wm = (warp >> 2) * 32;
        const int wn = (warp & 3) * 32;
        const int g  = lane >> 2, tg = lane & 3;

        float acc[2][4][4];
        #pragma unroll
        for (int i = 0; i < 2; ++i)
            #pragma unroll
            for (int j = 0; j < 4; ++j)
                #pragma unroll
                for (int t = 0; t < 4; ++t) acc[i][j][t] = 0.f;

        #define DE_LOAD(s, kbase)                                                         \
            {                                                                              \
                { int m = tid >> 2, k4 = (tid & 3) << 2;                                   \
                  cp16(&DAS(s, m, k4), emb + (size_t)(bm0 + m) * DD + (kbase) + k4); }     \
                _Pragma("unroll")                                                          \
                for (int i_ = 0; i_ < 2; ++i_) {                                           \
                    int slot = tid + i_ * 256;                                             \
                    int n = slot >> 2, k4 = (slot & 3) << 2;                               \
                    cp16(&DPS(s, n, k4), protos + (size_t)(bn0 + n) * DD + (kbase) + k4);  \
                }                                                                          \
                CP_COMMIT();                                                               \
            }

        DE_LOAD(0, 0);
        int s = 0;
        const int NT = DD / 16;
        for (int kt = 0; kt < NT; ++kt) {
            if (kt + 1 < NT) { DE_LOAD(s ^ 1, (kt + 1) * 16); CP_WAIT(1); }
            else             { CP_WAIT(0); }
            __syncthreads();

            #pragma unroll
            for (int ks = 0; ks < 2; ++ks) {
                const int kb = ks * 8;
                uint32_t afr[2][4], bfr[4][2];
                #pragma unroll
                for (int i = 0; i < 2; ++i) {
                    int m0 = wm + i * 16;
                    afr[i][0] = f2tf(DAS(s, m0 + g,     kb + tg));
                    afr[i][1] = f2tf(DAS(s, m0 + g + 8, kb + tg));
                    afr[i][2] = f2tf(DAS(s, m0 + g,     kb + tg + 4));
                    afr[i][3] = f2tf(DAS(s, m0 + g + 8, kb + tg + 4));
                }
                #pragma unroll
                for (int j = 0; j < 4; ++j) {
                    int n0 = wn + j * 8;
                    bfr[j][0] = f2tf(DPS(s, n0 + g, kb + tg));
                    bfr[j][1] = f2tf(DPS(s, n0 + g, kb + tg + 4));
                }
                #pragma unroll
                for (int i = 0; i < 2; ++i)
                    #pragma unroll
                    for (int j = 0; j < 4; ++j)
                        mma_tf32(acc[i][j], afr[i], bfr[j]);
            }
            __syncthreads();
            s ^= 1;
        }

        #pragma unroll
        for (int i = 0; i < 2; ++i) {
            int r0 = bm0 + wm + i * 16 + g;
            #pragma unroll
            for (int j = 0; j < 4; ++j) {
                int col = bn0 + wn + j * 8 + 2 * tg;
                *(float2*)(g_dotep + (size_t)r0 * (CC * KK) + col)       = make_float2(acc[i][j][0], acc[i][j][1]);
                *(float2*)(g_dotep + (size_t)(r0 + 8) * (CC * KK) + col) = make_float2(acc[i][j][2], acc[i][j][3]);
            }
        }
        #undef DE_LOAD
        #undef DAS
        #undef DPS
    }
}

// ===========================================================================
// Kernel B (main, fused): per (64-batch-tile, class):
//   1. qW tile [64 x 256] = emb_tile @ W1top  (tf32 mma, acc in registers)
//   2. epilogue: scores[b][k] = sum_d w2[d]*tanh(qW+pt[k][d])
//   3. softmax over K, dist via Gram trick, write out
// grid (16, 32), 256 threads (8 warps, n-sliced: warp tile 64x32).
// 2 CTAs/SM: GEMM of one block overlaps MUFU epilogue of the other.
// ===========================================================================
__global__ __launch_bounds__(256, 2) void fused_main(
    const float* __restrict__ emb, const float* __restrict__ W1,
    const float* __restrict__ w2, const float* __restrict__ b2,
    const float* __restrict__ temperature, float* __restrict__ out)
{
    extern __shared__ float sh[];
    // phase-1 layout: As [2][64][20] = 2560 fl ; Bs [2][16][260] = 8320 fl
    float* Asb = sh;
    float* Bsb = sh + 2560;
    // phase-2 layout (aliases phase-1 region)
    float* sh_pt    = sh;                  // [16][256] = 4096
    float* sh_score = sh + 4096;           // [64][17]  = 1088
    float* sh_w2    = sh + 4096 + 1088;    // 256
    float* sh_G     = sh_w2 + 256;         // [16][17] = 272
    float* sh_inval = sh_G + 272;          // 16

    const int c  = blockIdx.y;
    const int b0 = blockIdx.x * 64;
    const float* A  = emb;
    const float* Bm = W1 + (size_t)c * TWO_D * DD;   // top half [256 k][256 n]

    const int tid  = threadIdx.x;
    const int warp = tid >> 5, lane = tid & 31;
    const int wn = warp * 32;            // warp n-slice (all 64 rows)
    const int g  = lane >> 2, tg = lane & 3;

    float acc[4][4][4];                  // [m16 tile][n8 tile][frag]
    #pragma unroll
    for (int i = 0; i < 4; ++i)
        #pragma unroll
        for (int j = 0; j < 4; ++j)
            #pragma unroll
            for (int t = 0; t < 4; ++t) acc[i][j][t] = 0.f;

    #define AS(s, m, k) Asb[(s) * 1280 + (m) * 20 + (k)]
    #define BS(s, k, n) Bsb[(s) * 4160 + (k) * 260 + (n)]
    #define FM_LOAD(s, kbase)                                                    \
        {                                                                         \
            { int m = tid >> 2, k4 = (tid & 3) << 2;                              \
              cp16(&AS(s, m, k4), A + (size_t)(b0 + m) * DD + (kbase) + k4); }    \
            _Pragma("unroll")                                                     \
            for (int i_ = 0; i_ < 4; ++i_) {                                      \
                int slot = tid + i_ * 256;                                        \
                int k = slot >> 6, n4 = (slot & 63) << 2;                         \
                cp16(&BS(s, k, n4), Bm + (size_t)((kbase) + k) * DD + n4);        \
            }                                                                     \
            CP_COMMIT();                                                          \
        }

    // ---------------- Phase 1: tf32 GEMM ----------------
    FM_LOAD(0, 0);
    int s = 0;
    const int NT = DD / 16;   // 16
    for (int kt = 0; kt < NT; ++kt) {
        if (kt + 1 < NT) { FM_LOAD(s ^ 1, (kt + 1) * 16); CP_WAIT(1); }
        else             { CP_WAIT(0); }
        __syncthreads();

        #pragma unroll
        for (int ks = 0; ks < 2; ++ks) {
            const int kb = ks * 8;
            uint32_t afr[4][4], bfr[4][2];
            #pragma unroll
            for (int i = 0; i < 4; ++i) {
                int m0 = i * 16;
                afr[i][0] = f2tf(AS(s, m0 + g,     kb + tg));
                afr[i][1] = f2tf(AS(s, m0 + g + 8, kb + tg));
                afr[i][2] = f2tf(AS(s, m0 + g,     kb + tg + 4));
                afr[i][3] = f2tf(AS(s, m0 + g + 8, kb + tg + 4));
            }
            #pragma unroll
            for (int j = 0; j < 4; ++j) {
                int n0 = wn + j * 8;
                bfr[j][0] = f2tf(BS(s, kb + tg,     n0 + g));
                bfr[j][1] = f2tf(BS(s, kb + tg + 4, n0 + g));
            }
            #pragma unroll
            for (int i = 0; i < 4; ++i)
                #pragma unroll
                for (int j = 0; j < 4; ++j)
                    mma_tf32(acc[i][j], afr[i], bfr[j]);
        }
        __syncthreads();
        s ^= 1;
    }
    // last iteration ended with __syncthreads() — safe to repurpose smem.

    // ---------------- Phase 2 tables ----------------
    {
        const float* ptg = g_proto_term + (size_t)c * KK * DD;
        #pragma unroll
        for (int i = 0; i < 16; ++i) sh_pt[tid + i * 256] = ptg[tid + i * 256];
        for (int i = tid; i < 64 * 17; i += 256) sh_score[i] = 0.f;
        if (tid < DD) sh_w2[tid] = w2[c * DD + tid];
        if (tid < KK * KK) sh_G[(tid >> 4) * 17 + (tid & 15)] = g_G[c * 256 + tid];
        if (tid < KK) sh_inval[tid] = g_inval[c * KK + tid];
    }
    __syncthreads();

    // per-thread w2 values for held columns
    float2 w2v[4];
    #pragma unroll
    for (int j = 0; j < 4; ++j)
        w2v[j] = *(float2*)&sh_w2[wn + j * 8 + 2 * tg];

    // ---------------- Phase 3: tanh scores ----------------
    #pragma unroll 1
    for (int k = 0; k < KK; ++k) {
        float2 ptv[4];
        #pragma unroll
        for (int j = 0; j < 4; ++j)
            ptv[j] = *(float2*)&sh_pt[k * DD + wn + j * 8 + 2 * tg];

        float part[8];
        #pragma unroll
        for (int i = 0; i < 4; ++i) {
            float p0 = 0.f, p1 = 0.f;
            #pragma unroll
            for (int j = 0; j < 4; ++j) {
                p0 = fmaf(w2v[j].x, tanh_fast(acc[i][j][0] + ptv[j].x), p0);
                p0 = fmaf(w2v[j].y, tanh_fast(acc[i][j][1] + ptv[j].y), p0);
                p1 = fmaf(w2v[j].x, tanh_fast(acc[i][j][2] + ptv[j].x), p1);
                p1 = fmaf(w2v[j].y, tanh_fast(acc[i][j][3] + ptv[j].y), p1);
            }
            part[2 * i]     = p0;
            part[2 * i + 1] = p1;
        }
        // reduce over tg (lane bits 0..1)
        #pragma unroll
        for (int r = 0; r < 8; ++r) {
            part[r] += __shfl_xor_sync(0xFFFFFFFFu, part[r], 1);
            part[r] += __shfl_xor_sync(0xFFFFFFFFu, part[r], 2);
        }
        if (tg == 0) {
            #pragma unroll
            for (int r = 0; r < 8; ++r) {
                int row = (r >> 1) * 16 + g + ((r & 1) << 3);
                atomicAdd(&sh_score[row * 17 + k], part[r]);
            }
        }
    }
    __syncthreads();

    // ---------------- Phase 4: softmax + Gram distance ----------------
    if (tid < 64) {
        const int b = b0 + tid;
        const float b2v  = b2[c];
        const float temp = temperature[0];

        float s16[KK];
        #pragma unroll
        for (int k = 0; k < KK; ++k)
            s16[k] = sh_score[tid * 17 + k] + b2v + sh_inval[k];

        float m = s16[0];
        #pragma unroll
        for (int k = 1; k < KK; ++k) m = fmaxf(m, s16[k]);
        float sum = 0.f;
        #pragma unroll
        for (int k = 0; k < KK; ++k) {
            float e = __expf(s16[k] - m);
            s16[k] = e;
            sum += e;
        }
        float inv = 1.f / sum;
        #pragma unroll
        for (int k = 0; k < KK; ++k) s16[k] *= inv;

        // dist^2 = e2 - 2*attn·dotep + attn^T G attn
        float depv[KK];
        const float4* dep = (const float4*)(g_dotep + (size_t)b * (CC * KK) + c * KK);
        #pragma unroll
        for (int q = 0; q < 4; ++q) {
            float4 v = dep[q];
            depv[4 * q + 0] = v.x; depv[4 * q + 1] = v.y;
            depv[4 * q + 2] = v.z; depv[4 * q + 3] = v.w;
        }
        float dist2 = g_e2[b];
        #pragma unroll
        for (int k = 0; k < KK; ++k)
            dist2 = fmaf(-2.0f * s16[k], depv[k], dist2);
        #pragma unroll
        for (int k = 0; k < KK; ++k) {
            float t = 0.f;
            #pragma unroll
            for (int k2 = 0; k2 < KK; ++k2)
                t = fmaf(sh_G[k * 17 + k2], s16[k2], t);
            dist2 = fmaf(s16[k], t, dist2);
        }
        out[(size_t)b * CC + c] = -sqrtf(fmaxf(dist2, 0.f)) * temp;
    }
    #undef AS
    #undef BS
    #undef FM_LOAD
}

// ---------------------------------------------------------------------------
extern "C" void kernel_launch(void* const* d_in, const int* in_sizes, int n_in,
                              void* d_out, int out_size)
{
    const float* emb    = (const float*)d_in[0];   // [B,D]
    const float* protos = (const float*)d_in[1];   // [C,K,D]
    const float* W1     = (const float*)d_in[2];   // [C,2D,D]
    const float* b1     = (const float*)d_in[3];   // [C,D]
    const float* w2     = (const float*)d_in[4];   // [C,D]
    const float* b2     = (const float*)d_in[5];   // [C]
    const float* temp   = (const float*)d_in[6];   // [1]
    const void*  valid  = (const void*)d_in[7];    // [C,K] bool (storage dtype unknown)
    float* out = (float*)d_out;                    // [B,C]

    const int dyn = (2 * 64 * 20 + 2 * 16 * 260) * 4;   // 43520 bytes
    cudaFuncSetAttribute(fused_main, cudaFuncAttributeMaxDynamicSharedMemorySize, dyn);

    prologue_kernel<<<257, 256>>>(emb, protos, W1, b1, valid);
    fused_main<<<dim3(16, CC), 256, dyn>>>(emb, W1, w2, b2, temp, out);
}